// round 4
// baseline (speedup 1.0000x reference)
#include <cuda_runtime.h>

#define Bn   16
#define Tn   262144
#define HOP  256
#define WINL 1024
#define PADL 384
#define Fn   1024          // Tn / HOP
#define Pn   22
#define NSEQ (Bn * Fn)     // 16384 independent filters

// Scratch device global (no allocation allowed in kernel_launch)
__device__ float d_frames[(size_t)NSEQ * WINL];  // 64MB: windowed synthesized frames

typedef unsigned long long ull;

static __device__ __forceinline__ ull pk2(float lo, float hi) {
    ull r; asm("mov.b64 %0,{%1,%2};" : "=l"(r) : "f"(lo), "f"(hi)); return r;
}
static __device__ __forceinline__ void upk2(float& lo, float& hi, ull v) {
    asm("mov.b64 {%0,%1},%2;" : "=f"(lo), "=f"(hi) : "l"(v));
}
static __device__ __forceinline__ ull fma2_(ull a, ull b, ull c) {
    ull r; asm("fma.rn.f32x2 %0,%1,%2,%3;" : "=l"(r) : "l"(a), "l"(b), "l"(c)); return r;
}
static __device__ __forceinline__ ull mul2_(ull a, ull b) {
    ull r; asm("mul.rn.f32x2 %0,%1,%2;" : "=l"(r) : "l"(a), "l"(b)); return r;
}
static __device__ __forceinline__ ull add2_(ull a, ull b) {
    ull r; asm("add.rn.f32x2 %0,%1,%2;" : "=l"(r) : "l"(a), "l"(b)); return r;
}

static __device__ __forceinline__ float hannf(int t) {
    return 0.5f - 0.5f * cosf(6.283185307179586f * (float)t * (1.0f / 1024.0f));
}

// ---------------------------------------------------------------------------
// Kernel 1: per-sequence LPC synthesis, 2-step blocked + packed f32x2 FMAs.
//   One thread per (b,f) sequence; warp = 32 consecutive frames of one batch.
//   - dot products split even/odd, H[0] term issued LAST (short critical path)
//   - x pair prefetched one block ahead via LDS.64
//   - (y0,y1) stored as one STS.64; smem padded to 34 for 8B alignment
// ---------------------------------------------------------------------------
__global__ void __launch_bounds__(128, 1)
lpc_kernel(const float* __restrict__ ex,
           const float* __restrict__ gain,
           const float* __restrict__ a) {
    __shared__ float xs  [4][32][34];  // [frame][time] staged excitation
    __shared__ float tile[4][32][34];  // [frame][time] synthesized outputs

    const int warp = threadIdx.x >> 5;
    const int lane = threadIdx.x & 31;
    const int gw   = blockIdx.x * 4 + warp;   // 0..511
    const int s0   = gw * 32;                 // warp-base sequence index
    const int s    = s0 + lane;
    const int b    = s >> 10;                 // Fn = 1024
    const int f0   = s0 & (Fn - 1);           // warp-base frame (same b whole warp)

    const float g = gain[s];

    // c[q] = -a[q-1] (q=1..22), c[23] = 0 ; d[q] = c1*c[q] + c[q+1]
    float c[24];
    #pragma unroll
    for (int p = 0; p < Pn; ++p) c[p + 1] = -a[s * Pn + p];
    c[23] = 0.0f;
    const float c1  = c[1];
    const float c1g = c1 * g;

    ull CA[11], CB[11], H[11];
    #pragma unroll
    for (int k = 0; k < 11; ++k) {
        const float dlo = fmaf(c1, c[2 * k + 1], c[2 * k + 2]);
        const float dhi = fmaf(c1, c[2 * k + 2], c[2 * k + 3]);
        CA[k] = pk2(c[2 * k + 1], c[2 * k + 2]);
        CB[k] = pk2(dlo, dhi);
        H[k]  = 0ull;   // zero initial state
    }

    const float* __restrict__ exb = ex + b * Tn;

    // prefetch chunk 0 (coalesced: lane sweeps time, r sweeps frames)
    float xr[32];
    #pragma unroll
    for (int r = 0; r < 32; ++r) {
        int idx = (f0 + r) * HOP + lane - PADL;
        xr[r] = ((unsigned)idx < (unsigned)Tn) ? exb[idx] : 0.0f;
    }

    for (int cchunk = 0; cchunk < 32; ++cchunk) {
        const int t0 = cchunk * 32;

        // commit prefetched chunk to smem (xs[frame][time], conflict-free)
        #pragma unroll
        for (int r = 0; r < 32; ++r) xs[warp][r][lane] = xr[r];
        __syncwarp();

        // issue next chunk's global loads now; latency hides under recurrence
        if (cchunk < 31) {
            const int t1 = t0 + 32;
            #pragma unroll
            for (int r = 0; r < 32; ++r) {
                int idx = (f0 + r) * HOP + t1 + lane - PADL;
                xr[r] = ((unsigned)idx < (unsigned)Tn) ? exb[idx] : 0.0f;
            }
        }

        // 16 blocks x 2 samples
        const float* xrow = &xs[warp][lane][0];
        float2 xp2 = *(const float2*)xrow;          // block 0 pair
        #pragma unroll
        for (int bk = 0; bk < 16; ++bk) {
            float2 xn2;
            if (bk < 15) xn2 = *(const float2*)(xrow + 2 * bk + 2);

            const float x0 = xp2.x, x1 = xp2.y;
            const float pre = c1g * x0;            // off critical path

            // even-lag partials, H[0] LAST (shortest path from newest state)
            ull ae = mul2_(CA[10], H[10]);
            ull be = mul2_(CB[10], H[10]);
            ae = fma2_(CA[8], H[8], ae);  be = fma2_(CB[8], H[8], be);
            ae = fma2_(CA[6], H[6], ae);  be = fma2_(CB[6], H[6], be);
            ae = fma2_(CA[4], H[4], ae);  be = fma2_(CB[4], H[4], be);
            ae = fma2_(CA[2], H[2], ae);  be = fma2_(CB[2], H[2], be);
            // odd-lag partials (independent chain)
            ull ao = mul2_(CA[9], H[9]);
            ull bo = mul2_(CB[9], H[9]);
            ao = fma2_(CA[7], H[7], ao);  bo = fma2_(CB[7], H[7], bo);
            ao = fma2_(CA[5], H[5], ao);  bo = fma2_(CB[5], H[5], bo);
            ao = fma2_(CA[3], H[3], ao);  bo = fma2_(CB[3], H[3], bo);
            ao = fma2_(CA[1], H[1], ao);  bo = fma2_(CB[1], H[1], bo);
            // newest pair last
            ae = fma2_(CA[0], H[0], ae);
            be = fma2_(CB[0], H[0], be);

            const ull accA = add2_(ae, ao);
            const ull accB = add2_(be, bo);
            float aLo, aHi, bLo, bHi;
            upk2(aLo, aHi, accA);
            upk2(bLo, bHi, accB);

            const float y0 = fmaf(g, x0, aLo + aHi);
            const float y1 = fmaf(g, x1, (bLo + bHi) + pre);

            *(float2*)(&tile[warp][lane][2 * bk]) = make_float2(y0, y1);

            // shift history by one pair; new pair = (y1, y0)
            #pragma unroll
            for (int k = 10; k > 0; --k) H[k] = H[k - 1];
            H[0] = pk2(y1, y0);

            xp2 = xn2;
        }
        __syncwarp();

        // transpose read + window + coalesced frame write
        const float wv = hannf(t0 + lane);
        float* __restrict__ fout = d_frames + (size_t)s0 * WINL + t0 + lane;
        #pragma unroll
        for (int r = 0; r < 32; ++r)
            fout[(size_t)r * WINL] = tile[warp][r][lane] * wv;
        __syncwarp();
    }
}

// ---------------------------------------------------------------------------
// Kernel 2: gather-OLA. Each output sample = sum of exactly <=4 frame samples.
//   Interior norm is exactly 2.0 (4-phase periodic Hann identity); edges use
//   inline hann. float4 everywhere (group never crosses frame edge: 4 | HOP).
// ---------------------------------------------------------------------------
__global__ void final_kernel(float* __restrict__ out) {
    const int i = blockIdx.x * blockDim.x + threadIdx.x;   // float4 group id
    if (i >= Bn * Tn / 4) return;
    const int b   = i >> 16;                // Tn/4 = 65536 groups per batch
    const int n0  = (i & 65535) << 2;
    const int pos = n0 + PADL;
    const int fhi = pos >> 8;               // HOP = 256; constant across group

    const float* __restrict__ fb = d_frames + (size_t)b * Fn * WINL;
    float4 acc = make_float4(0.f, 0.f, 0.f, 0.f);
    #pragma unroll
    for (int k = 0; k < 4; ++k) {
        const int ff = fhi - k;
        if (ff >= 0 && ff < Fn) {
            const float4 v = *(const float4*)(fb + (size_t)ff * WINL + (pos - ff * HOP));
            acc.x += v.x; acc.y += v.y; acc.z += v.z; acc.w += v.w;
        }
    }

    float4 o;
    if (pos >= 3 * HOP && fhi <= Fn - 1) {           // interior: norm == 2
        o.x = acc.x * 0.5f; o.y = acc.y * 0.5f;
        o.z = acc.z * 0.5f; o.w = acc.w * 0.5f;
    } else {                                         // 2x384 samples per batch
        float nrm[4] = {0.f, 0.f, 0.f, 0.f};
        #pragma unroll
        for (int j = 0; j < 4; ++j) {
            #pragma unroll
            for (int k = 0; k < 4; ++k) {
                const int ff = fhi - k;
                if (ff >= 0 && ff < Fn) nrm[j] += hannf(pos + j - ff * HOP);
            }
        }
        o.x = acc.x / nrm[0]; o.y = acc.y / nrm[1];
        o.z = acc.z / nrm[2]; o.w = acc.w / nrm[3];
    }
    ((float4*)out)[i] = o;
}

// ---------------------------------------------------------------------------
extern "C" void kernel_launch(void* const* d_in, const int* in_sizes, int n_in,
                              void* d_out, int out_size) {
    const float* ex   = (const float*)d_in[0];
    const float* gain = (const float*)d_in[1];
    const float* a    = (const float*)d_in[2];
    float* out = (float*)d_out;

    lpc_kernel<<<128, 128>>>(ex, gain, a);
    final_kernel<<<(Bn * Tn / 4 + 255) / 256, 256>>>(out);
}